// round 3
// baseline (speedup 1.0000x reference)
#include <cuda_runtime.h>
#include <cstdint>
#include <cstddef>

#define B_TOT 512
#define S_LEN 256
#define T_TAG 128
#define NB 4
#define NCTA (B_TOT / NB)      // 128 CTAs
#define NTHREADS 128
#define SMEM_FLOATS (T_TAG * T_TAG + T_TAG * NB + 32)
#define SMEM_BYTES (SMEM_FLOATS * 4)

__device__ float g_partial[NCTA];

__device__ __forceinline__ float warp_max(float v) {
#pragma unroll
    for (int o = 16; o > 0; o >>= 1)
        v = fmaxf(v, __shfl_xor_sync(0xffffffffu, v, o));
    return v;
}

__device__ __forceinline__ float warp_sum(float v) {
#pragma unroll
    for (int o = 16; o > 0; o >>= 1)
        v += __shfl_xor_sync(0xffffffffu, v, o);
    return v;
}

__global__ __launch_bounds__(NTHREADS, 1) void crf_main(
    const float* __restrict__ emis,
    const void* __restrict__ tags_raw,
    const void* __restrict__ mask_raw,
    const float* __restrict__ trans)
{
    extern __shared__ float sh[];
    float* E_sh = sh;                       // [T_TAG][T_TAG] = exp(trans)
    float* p_sh = sh + T_TAG * T_TAG;       // [T_TAG][NB]
    float* red  = p_sh + T_TAG * NB;        // reduction scratch

    const int tid  = threadIdx.x;           // = tag column j
    const int lane = tid & 31;
    const int wid  = tid >> 5;
    const int b0   = blockIdx.x * NB;

    // ---- dtype probes (deterministic, input-derived) ----
    // tags: if the buffer is int64, every odd 32-bit word is 0 (values are 0..127).
    const int* t32 = (const int*)tags_raw;
    const int tags_is_i32 = __syncthreads_or(t32[2 * tid + 1] != 0);
    // mask: u8 all-ones reads 0x01010101 as int; int32 all-ones reads 1.
    const int* m32 = (const int*)mask_raw;
    const unsigned char* m8 = (const unsigned char*)mask_raw;
    const bool mask_is_u8 = (m32[0] == 0x01010101);

    // ---- E = exp(trans), one-time per CTA ----
    for (int idx = tid; idx < T_TAG * T_TAG; idx += NTHREADS)
        E_sh[idx] = __expf(trans[idx]);

    const size_t eb0 = (size_t)(b0 + 0) * S_LEN * T_TAG;
    const size_t eb1 = (size_t)(b0 + 1) * S_LEN * T_TAG;
    const size_t eb2 = (size_t)(b0 + 2) * S_LEN * T_TAG;
    const size_t eb3 = (size_t)(b0 + 3) * S_LEN * T_TAG;
    const size_t mb0 = (size_t)(b0 + 0) * S_LEN;
    const size_t mb1 = (size_t)(b0 + 1) * S_LEN;
    const size_t mb2 = (size_t)(b0 + 2) * S_LEN;
    const size_t mb3 = (size_t)(b0 + 3) * S_LEN;

#define MASK_AT(idx) (mask_is_u8 ? (m8[idx] != 0) : (m32[idx] != 0))
#define TAG_AT(idx)  (tags_is_i32 ? t32[idx] : t32[2 * (idx)])

    // ---- alpha_0 = emissions[:, 0, :] ----
    float a0 = emis[eb0 + tid];
    float a1 = emis[eb1 + tid];
    float a2 = emis[eb2 + tid];
    float a3 = emis[eb3 + tid];

    float m0, m1, m2, m3;

    // initial epilogue: m = max_j alpha, p = exp(alpha - m)
    {
        float w0 = warp_max(a0), w1 = warp_max(a1), w2 = warp_max(a2), w3 = warp_max(a3);
        if (lane == 0) {
            red[wid * 4 + 0] = w0; red[wid * 4 + 1] = w1;
            red[wid * 4 + 2] = w2; red[wid * 4 + 3] = w3;
        }
        __syncthreads();   // also covers E_sh writes
        m0 = fmaxf(fmaxf(red[0], red[4]),  fmaxf(red[8],  red[12]));
        m1 = fmaxf(fmaxf(red[1], red[5]),  fmaxf(red[9],  red[13]));
        m2 = fmaxf(fmaxf(red[2], red[6]),  fmaxf(red[10], red[14]));
        m3 = fmaxf(fmaxf(red[3], red[7]),  fmaxf(red[11], red[15]));
        ((float4*)p_sh)[tid] = make_float4(__expf(a0 - m0), __expf(a1 - m1),
                                           __expf(a2 - m2), __expf(a3 - m3));
        __syncthreads();
    }

    // ---- forward recursion ----
    for (int t = 1; t < S_LEN; t++) {
        // prefetch emissions & mask for this step (hidden under the FMA loop)
        const size_t toff = (size_t)t * T_TAG + tid;
        float em0 = emis[eb0 + toff];
        float em1 = emis[eb1 + toff];
        float em2 = emis[eb2 + toff];
        float em3 = emis[eb3 + toff];
        bool k0 = MASK_AT(mb0 + t);
        bool k1 = MASK_AT(mb1 + t);
        bool k2 = MASK_AT(mb2 + t);
        bool k3 = MASK_AT(mb3 + t);

        float acc0 = 0.f, acc1 = 0.f, acc2 = 0.f, acc3 = 0.f;
        const float4* p4 = (const float4*)p_sh;
#pragma unroll 32
        for (int i = 0; i < T_TAG; i++) {
            float4 p = p4[i];                       // broadcast
            float  e = E_sh[i * T_TAG + tid];       // conflict-free
            acc0 = fmaf(p.x, e, acc0);
            acc1 = fmaf(p.y, e, acc1);
            acc2 = fmaf(p.z, e, acc2);
            acc3 = fmaf(p.w, e, acc3);
        }

        if (k0) a0 = m0 + __logf(acc0) + em0;
        if (k1) a1 = m1 + __logf(acc1) + em1;
        if (k2) a2 = m2 + __logf(acc2) + em2;
        if (k3) a3 = m3 + __logf(acc3) + em3;

        // epilogue: new m, new p
        float w0 = warp_max(a0), w1 = warp_max(a1), w2 = warp_max(a2), w3 = warp_max(a3);
        if (lane == 0) {
            red[wid * 4 + 0] = w0; red[wid * 4 + 1] = w1;
            red[wid * 4 + 2] = w2; red[wid * 4 + 3] = w3;
        }
        __syncthreads();   // all reads of p_sh done; red visible
        m0 = fmaxf(fmaxf(red[0], red[4]),  fmaxf(red[8],  red[12]));
        m1 = fmaxf(fmaxf(red[1], red[5]),  fmaxf(red[9],  red[13]));
        m2 = fmaxf(fmaxf(red[2], red[6]),  fmaxf(red[10], red[14]));
        m3 = fmaxf(fmaxf(red[3], red[7]),  fmaxf(red[11], red[15]));
        ((float4*)p_sh)[tid] = make_float4(__expf(a0 - m0), __expf(a1 - m1),
                                           __expf(a2 - m2), __expf(a3 - m3));
        __syncthreads();   // p_sh ready for next step
    }

    // ---- log_Z per batch ----
    float s0 = warp_sum(__expf(a0 - m0));
    float s1 = warp_sum(__expf(a1 - m1));
    float s2 = warp_sum(__expf(a2 - m2));
    float s3 = warp_sum(__expf(a3 - m3));
    if (lane == 0) {
        red[wid * 4 + 0] = s0; red[wid * 4 + 1] = s1;
        red[wid * 4 + 2] = s2; red[wid * 4 + 3] = s3;
    }
    __syncthreads();
    float z0 = m0 + __logf(red[0] + red[4] + red[8]  + red[12]);
    float z1 = m1 + __logf(red[1] + red[5] + red[9]  + red[13]);
    float z2 = m2 + __logf(red[2] + red[6] + red[10] + red[14]);
    float z3 = m3 + __logf(red[3] + red[7] + red[11] + red[15]);

    // ---- gold score ----
    float gg[NB] = {0.f, 0.f, 0.f, 0.f};
#pragma unroll
    for (int nb = 0; nb < NB; nb++) {
        const size_t tb = (size_t)(b0 + nb) * S_LEN;
        const size_t ebn = (size_t)(b0 + nb) * S_LEN * T_TAG;
        float g = 0.f;
        for (int tt = tid; tt < S_LEN; tt += NTHREADS) {
            int tag = TAG_AT(tb + tt);
            bool mk = MASK_AT(tb + tt);
            if (mk) g += emis[ebn + (size_t)tt * T_TAG + tag];
            if (tt + 1 < S_LEN) {
                bool mk2 = MASK_AT(tb + tt + 1);
                if (mk && mk2) g += trans[tag * T_TAG + TAG_AT(tb + tt + 1)];
            }
        }
        gg[nb] = g;
    }
    __syncthreads();   // red reads above complete before reuse
    float q0 = warp_sum(gg[0]);
    float q1 = warp_sum(gg[1]);
    float q2 = warp_sum(gg[2]);
    float q3 = warp_sum(gg[3]);
    if (lane == 0) {
        red[wid * 4 + 0] = q0; red[wid * 4 + 1] = q1;
        red[wid * 4 + 2] = q2; red[wid * 4 + 3] = q3;
    }
    __syncthreads();
    if (tid == 0) {
        float gold0 = red[0] + red[4] + red[8]  + red[12];
        float gold1 = red[1] + red[5] + red[9]  + red[13];
        float gold2 = red[2] + red[6] + red[10] + red[14];
        float gold3 = red[3] + red[7] + red[11] + red[15];
        g_partial[blockIdx.x] = (z0 - gold0) + (z1 - gold1) + (z2 - gold2) + (z3 - gold3);
    }
#undef MASK_AT
#undef TAG_AT
}

__global__ void crf_final(float* __restrict__ out) {
    const int tid = threadIdx.x;   // 128 threads
    float v = g_partial[tid];
    v = warp_sum(v);
    __shared__ float s[4];
    if ((tid & 31) == 0) s[tid >> 5] = v;
    __syncthreads();
    if (tid == 0)
        out[0] = (s[0] + s[1] + s[2] + s[3]) * (1.0f / (float)B_TOT);
}

extern "C" void kernel_launch(void* const* d_in, const int* in_sizes, int n_in,
                              void* d_out, int out_size) {
    const float* emis  = (const float*)d_in[0];
    const void*  tags  = d_in[1];
    const void*  mask  = d_in[2];
    const float* trans = (const float*)d_in[3];
    float* out = (float*)d_out;

    cudaFuncSetAttribute(crf_main, cudaFuncAttributeMaxDynamicSharedMemorySize, SMEM_BYTES);
    crf_main<<<NCTA, NTHREADS, SMEM_BYTES>>>(emis, tags, mask, trans);
    crf_final<<<1, NTHREADS>>>(out);
}

// round 4
// speedup vs baseline: 1.3117x; 1.3117x over previous
#include <cuda_runtime.h>
#include <cstdint>
#include <cstddef>

#define B_TOT 512
#define S_LEN 256
#define T_TAG 128
#define NB 4
#define NCTA (B_TOT / NB)      // 128 CTAs
#define NTHREADS 128

__device__ float g_partial[NCTA];

__device__ __forceinline__ float warp_max(float v) {
#pragma unroll
    for (int o = 16; o > 0; o >>= 1)
        v = fmaxf(v, __shfl_xor_sync(0xffffffffu, v, o));
    return v;
}

__device__ __forceinline__ float warp_sum(float v) {
#pragma unroll
    for (int o = 16; o > 0; o >>= 1)
        v += __shfl_xor_sync(0xffffffffu, v, o);
    return v;
}

// packed f32x2 helpers
__device__ __forceinline__ unsigned long long dup2(float e) {
    unsigned long long r;
    asm("mov.b64 %0, {%1, %1};" : "=l"(r) : "f"(e));
    return r;
}
__device__ __forceinline__ void fma2(unsigned long long& acc, unsigned long long a,
                                     unsigned long long b) {
    asm("fma.rn.f32x2 %0, %1, %2, %0;" : "+l"(acc) : "l"(a), "l"(b));
}
__device__ __forceinline__ unsigned long long add2(unsigned long long a,
                                                   unsigned long long b) {
    unsigned long long r;
    asm("add.rn.f32x2 %0, %1, %2;" : "=l"(r) : "l"(a), "l"(b));
    return r;
}
__device__ __forceinline__ void unpack2(unsigned long long v, float& lo, float& hi) {
    asm("mov.b64 {%0, %1}, %2;" : "=f"(lo), "=f"(hi) : "l"(v));
}

__global__ __launch_bounds__(NTHREADS, 1) void crf_main(
    const float* __restrict__ emis,
    const void* __restrict__ tags_raw,
    const void* __restrict__ mask_raw,
    const float* __restrict__ trans)
{
    __shared__ float4 p_sh[2][T_TAG];     // [buf][i] = p for 4 batches, 4KB
    __shared__ float4 red4[2][4];         // [buf][warp] = warp maxes for 4 batches
    __shared__ float4 scr4[4];            // final reductions

    const int tid  = threadIdx.x;         // = tag column j
    const int lane = tid & 31;
    const int wid  = tid >> 5;
    const int b0   = blockIdx.x * NB;

    // ---- dtype probes (deterministic, input-derived) ----
    const int* t32 = (const int*)tags_raw;
    const int tags_is_i32 = __syncthreads_or(t32[2 * tid + 1] != 0);
    const int* m32 = (const int*)mask_raw;
    const unsigned char* m8 = (const unsigned char*)mask_raw;
    const bool mask_is_u8 = (m32[0] == 0x01010101);

#define MASK_AT(idx) (mask_is_u8 ? (m8[idx] != 0) : (m32[idx] != 0))
#define TAG_AT(idx)  (tags_is_i32 ? t32[idx] : t32[2 * (idx)])

    // ---- E column j into registers: Ereg[i] = exp(trans[i][j]) ----
    float Ereg[T_TAG];
#pragma unroll
    for (int i = 0; i < T_TAG; i++)
        Ereg[i] = __expf(trans[i * T_TAG + tid]);

    const size_t eb0 = (size_t)(b0 + 0) * S_LEN * T_TAG;
    const size_t eb1 = (size_t)(b0 + 1) * S_LEN * T_TAG;
    const size_t eb2 = (size_t)(b0 + 2) * S_LEN * T_TAG;
    const size_t eb3 = (size_t)(b0 + 3) * S_LEN * T_TAG;
    const size_t mb0 = (size_t)(b0 + 0) * S_LEN;
    const size_t mb1 = (size_t)(b0 + 1) * S_LEN;
    const size_t mb2 = (size_t)(b0 + 2) * S_LEN;
    const size_t mb3 = (size_t)(b0 + 3) * S_LEN;

    // ---- alpha_0 = emissions[:, 0, :] ----
    float a0 = emis[eb0 + tid];
    float a1 = emis[eb1 + tid];
    float a2 = emis[eb2 + tid];
    float a3 = emis[eb3 + tid];

    // bootstrap: m_init, p(1), red[0] = warp maxes of alpha_0
    float mn0, mn1, mn2, mn3;   // m currently normalizing p_cur
    {
        float w0 = warp_max(a0), w1 = warp_max(a1), w2 = warp_max(a2), w3 = warp_max(a3);
        if (lane == 0) red4[0][wid] = make_float4(w0, w1, w2, w3);
        __syncthreads();
        float4 r0 = red4[0][0], r1 = red4[0][1], r2 = red4[0][2], r3 = red4[0][3];
        mn0 = fmaxf(fmaxf(r0.x, r1.x), fmaxf(r2.x, r3.x));
        mn1 = fmaxf(fmaxf(r0.y, r1.y), fmaxf(r2.y, r3.y));
        mn2 = fmaxf(fmaxf(r0.z, r1.z), fmaxf(r2.z, r3.z));
        mn3 = fmaxf(fmaxf(r0.w, r1.w), fmaxf(r2.w, r3.w));
        p_sh[0][tid] = make_float4(__expf(a0 - mn0), __expf(a1 - mn1),
                                   __expf(a2 - mn2), __expf(a3 - mn3));
        __syncthreads();
    }

    // prefetch step t=1 emissions + mask
    float em0, em1, em2, em3;
    bool  k0, k1, k2, k3;
    {
        const size_t toff = (size_t)1 * T_TAG + tid;
        em0 = emis[eb0 + toff]; em1 = emis[eb1 + toff];
        em2 = emis[eb2 + toff]; em3 = emis[eb3 + toff];
        k0 = MASK_AT(mb0 + 1); k1 = MASK_AT(mb1 + 1);
        k2 = MASK_AT(mb2 + 1); k3 = MASK_AT(mb3 + 1);
    }

    // ---- forward recursion: ONE barrier per step ----
    for (int t = 1; t < S_LEN; t++) {
        const int cur = (t - 1) & 1;
        const int nxt = t & 1;

        // prefetch t+1 (consumed next iteration; hides DRAM latency under loop)
        float emN0 = 0.f, emN1 = 0.f, emN2 = 0.f, emN3 = 0.f;
        bool  kN0 = false, kN1 = false, kN2 = false, kN3 = false;
        if (t + 1 < S_LEN) {
            const size_t toff = (size_t)(t + 1) * T_TAG + tid;
            emN0 = emis[eb0 + toff]; emN1 = emis[eb1 + toff];
            emN2 = emis[eb2 + toff]; emN3 = emis[eb3 + toff];
            kN0 = MASK_AT(mb0 + t + 1); kN1 = MASK_AT(mb1 + t + 1);
            kN2 = MASK_AT(mb2 + t + 1); kN3 = MASK_AT(mb3 + t + 1);
        }

        // m_next = max(alpha_{t-1}) from red[cur] (written before last barrier)
        float4 r0 = red4[cur][0], r1 = red4[cur][1], r2 = red4[cur][2], r3 = red4[cur][3];
        const float mN0 = fmaxf(fmaxf(r0.x, r1.x), fmaxf(r2.x, r3.x));
        const float mN1 = fmaxf(fmaxf(r0.y, r1.y), fmaxf(r2.y, r3.y));
        const float mN2 = fmaxf(fmaxf(r0.z, r1.z), fmaxf(r2.z, r3.z));
        const float mN3 = fmaxf(fmaxf(r0.w, r1.w), fmaxf(r2.w, r3.w));

        // ---- acc_j(b) = sum_i p[i][b] * E[i][j], packed f32x2 over batch pairs ----
        unsigned long long accA01 = 0ull, accA23 = 0ull;  // even i
        unsigned long long accB01 = 0ull, accB23 = 0ull;  // odd i
        const ulonglong2* pp = (const ulonglong2*)&p_sh[cur][0];
#pragma unroll
        for (int i = 0; i < T_TAG; i += 2) {
            ulonglong2 pa = pp[i];
            unsigned long long ea = dup2(Ereg[i]);
            fma2(accA01, ea, pa.x);
            fma2(accA23, ea, pa.y);
            ulonglong2 pb = pp[i + 1];
            unsigned long long eb = dup2(Ereg[i + 1]);
            fma2(accB01, eb, pb.x);
            fma2(accB23, eb, pb.y);
        }
        float A0, A1, A2, A3;
        unpack2(add2(accA01, accB01), A0, A1);
        unpack2(add2(accA23, accB23), A2, A3);

        // alpha update (mn = norm of p_cur)
        if (k0) a0 = mn0 + __logf(A0) + em0;
        if (k1) a1 = mn1 + __logf(A1) + em1;
        if (k2) a2 = mn2 + __logf(A2) + em2;
        if (k3) a3 = mn3 + __logf(A3) + em3;

        // build p_next normalized with m_next (deferred max — exact for any m)
        mn0 = mN0; mn1 = mN1; mn2 = mN2; mn3 = mN3;
        p_sh[nxt][tid] = make_float4(__expf(a0 - mn0), __expf(a1 - mn1),
                                     __expf(a2 - mn2), __expf(a3 - mn3));

        // publish this step's warp maxes (consumed NEXT step, off critical path)
        float w0 = warp_max(a0), w1 = warp_max(a1), w2 = warp_max(a2), w3 = warp_max(a3);
        if (lane == 0) red4[nxt][wid] = make_float4(w0, w1, w2, w3);

        em0 = emN0; em1 = emN1; em2 = emN2; em3 = emN3;
        k0 = kN0; k1 = kN1; k2 = kN2; k3 = kN3;

        __syncthreads();   // p_next + red_next visible
    }

    // ---- log_Z per batch (mn is a valid shift: |a - mn| bounded) ----
    float s0 = warp_sum(__expf(a0 - mn0));
    float s1 = warp_sum(__expf(a1 - mn1));
    float s2 = warp_sum(__expf(a2 - mn2));
    float s3 = warp_sum(__expf(a3 - mn3));
    if (lane == 0) scr4[wid] = make_float4(s0, s1, s2, s3);
    __syncthreads();
    float4 q0 = scr4[0], q1 = scr4[1], q2 = scr4[2], q3 = scr4[3];
    const float z0 = mn0 + __logf(q0.x + q1.x + q2.x + q3.x);
    const float z1 = mn1 + __logf(q0.y + q1.y + q2.y + q3.y);
    const float z2 = mn2 + __logf(q0.z + q1.z + q2.z + q3.z);
    const float z3 = mn3 + __logf(q0.w + q1.w + q2.w + q3.w);

    // ---- gold score ----
    float gg[NB] = {0.f, 0.f, 0.f, 0.f};
#pragma unroll
    for (int nb = 0; nb < NB; nb++) {
        const size_t tb = (size_t)(b0 + nb) * S_LEN;
        const size_t ebn = (size_t)(b0 + nb) * S_LEN * T_TAG;
        float g = 0.f;
        for (int tt = tid; tt < S_LEN; tt += NTHREADS) {
            int tag = TAG_AT(tb + tt);
            bool mk = MASK_AT(tb + tt);
            if (mk) g += emis[ebn + (size_t)tt * T_TAG + tag];
            if (tt + 1 < S_LEN) {
                bool mk2 = MASK_AT(tb + tt + 1);
                if (mk && mk2) g += trans[tag * T_TAG + TAG_AT(tb + tt + 1)];
            }
        }
        gg[nb] = g;
    }
    __syncthreads();   // scr4 reads above complete before reuse
    float g0 = warp_sum(gg[0]);
    float g1 = warp_sum(gg[1]);
    float g2 = warp_sum(gg[2]);
    float g3 = warp_sum(gg[3]);
    if (lane == 0) scr4[wid] = make_float4(g0, g1, g2, g3);
    __syncthreads();
    if (tid == 0) {
        float4 u0 = scr4[0], u1 = scr4[1], u2 = scr4[2], u3 = scr4[3];
        float gold0 = u0.x + u1.x + u2.x + u3.x;
        float gold1 = u0.y + u1.y + u2.y + u3.y;
        float gold2 = u0.z + u1.z + u2.z + u3.z;
        float gold3 = u0.w + u1.w + u2.w + u3.w;
        g_partial[blockIdx.x] = (z0 - gold0) + (z1 - gold1) + (z2 - gold2) + (z3 - gold3);
    }
#undef MASK_AT
#undef TAG_AT
}

__global__ void crf_final(float* __restrict__ out) {
    const int tid = threadIdx.x;   // 128 threads
    float v = g_partial[tid];
    v = warp_sum(v);
    __shared__ float s[4];
    if ((tid & 31) == 0) s[tid >> 5] = v;
    __syncthreads();
    if (tid == 0)
        out[0] = (s[0] + s[1] + s[2] + s[3]) * (1.0f / (float)B_TOT);
}

extern "C" void kernel_launch(void* const* d_in, const int* in_sizes, int n_in,
                              void* d_out, int out_size) {
    const float* emis  = (const float*)d_in[0];
    const void*  tags  = d_in[1];
    const void*  mask  = d_in[2];
    const float* trans = (const float*)d_in[3];
    float* out = (float*)d_out;

    crf_main<<<NCTA, NTHREADS>>>(emis, tags, mask, trans);
    crf_final<<<1, NTHREADS>>>(out);
}

// round 5
// speedup vs baseline: 1.5536x; 1.1844x over previous
#include <cuda_runtime.h>
#include <cstdint>
#include <cstddef>

#define B_TOT 512
#define S_LEN 256
#define T_TAG 128
#define NB 4
#define NCTA 128
#define NTHREADS 256

__device__ float g_partial[NCTA];
__device__ int g_count = 0;

__device__ __forceinline__ float warp_max(float v) {
#pragma unroll
    for (int o = 16; o > 0; o >>= 1)
        v = fmaxf(v, __shfl_xor_sync(0xffffffffu, v, o));
    return v;
}
__device__ __forceinline__ float warp_sum(float v) {
#pragma unroll
    for (int o = 16; o > 0; o >>= 1)
        v += __shfl_xor_sync(0xffffffffu, v, o);
    return v;
}
__device__ __forceinline__ unsigned long long dup2(float e) {
    unsigned long long r;
    asm("mov.b64 %0, {%1, %1};" : "=l"(r) : "f"(e));
    return r;
}
__device__ __forceinline__ void fma2(unsigned long long& acc, unsigned long long a,
                                     unsigned long long b) {
    asm("fma.rn.f32x2 %0, %1, %2, %0;" : "+l"(acc) : "l"(a), "l"(b));
}
__device__ __forceinline__ unsigned long long add2(unsigned long long a,
                                                   unsigned long long b) {
    unsigned long long r;
    asm("add.rn.f32x2 %0, %1, %2;" : "=l"(r) : "l"(a), "l"(b));
    return r;
}
__device__ __forceinline__ void unpack2(unsigned long long v, float& lo, float& hi) {
    asm("mov.b64 {%0, %1}, %2;" : "=f"(lo), "=f"(hi) : "l"(v));
}

__global__ __launch_bounds__(NTHREADS, 1) void crf_main(
    const float* __restrict__ emis,
    const void* __restrict__ tags_raw,
    const void* __restrict__ mask_raw,
    const float* __restrict__ trans,
    float* __restrict__ out)
{
    __shared__ float4 p_sh[T_TAG];                 // p for 4 batches
    __shared__ unsigned long long xch01[T_TAG];    // B's partial for pair (b0,b1)
    __shared__ unsigned long long xch23[T_TAG];    // A's partial for pair (b2,b3)
    __shared__ float2 red_sh[8];                   // per-warp maxes (x=low batch, y=high)
    __shared__ float scr[2];
    __shared__ int is_last;

    const int tid  = threadIdx.x;
    const int lane = tid & 31;
    const int wid  = tid >> 5;
    const int g    = tid >> 7;         // 0: warps 0-3 (batches b0,b1), 1: warps 4-7 (b2,b3)
    const int j    = tid & 127;        // tag column
    const int rb   = g * 4;
    const int b0   = blockIdx.x * NB;

    // ---- dtype probes (input-derived, deterministic) ----
    const int* t32 = (const int*)tags_raw;
    const int tags_is_i32 = __syncthreads_or(t32[2 * tid + 1] != 0);
    const int* m32 = (const int*)mask_raw;
    const unsigned char* m8 = (const unsigned char*)mask_raw;
    const bool mask_is_u8 = (m32[0] == 0x01010101);

#define MASK_AT(idx) (mask_is_u8 ? (m8[idx] != 0) : (m32[idx] != 0))
#define TAG_AT(idx)  (tags_is_i32 ? t32[idx] : t32[2 * (idx)])

    // ---- E column j, my half of i, pre-duplicated f32x2 in registers ----
    const int ibase = g * 64;
    unsigned long long E2[64];
#pragma unroll
    for (int ii = 0; ii < 64; ii++)
        E2[ii] = dup2(__expf(trans[(ibase + ii) * T_TAG + j]));

    const int bL = b0 + g * 2, bH = bL + 1;        // my two batches
    const size_t ebL = (size_t)bL * S_LEN * T_TAG;
    const size_t ebH = (size_t)bH * S_LEN * T_TAG;
    const size_t mbL = (size_t)bL * S_LEN;
    const size_t mbH = (size_t)bH * S_LEN;

    // ---- alpha_0 ----
    float aL = emis[ebL + j];
    float aH = emis[ebH + j];
    float mnL, mnH;
    {
        float wl = warp_max(aL), wh = warp_max(aH);
        if (lane == 0) red_sh[wid] = make_float2(wl, wh);
        __syncthreads();
        float2 r0 = red_sh[rb], r1 = red_sh[rb + 1], r2 = red_sh[rb + 2], r3 = red_sh[rb + 3];
        mnL = fmaxf(fmaxf(r0.x, r1.x), fmaxf(r2.x, r3.x));
        mnH = fmaxf(fmaxf(r0.y, r1.y), fmaxf(r2.y, r3.y));
        float2* pj = (float2*)&p_sh[j] + g;
        *pj = make_float2(__expf(aL - mnL), __expf(aH - mnH));
        __syncthreads();   // p + red (red still holds max(alpha_0), reused as mN at t=1)
    }

    // prefetch t=1
    float emL = emis[ebL + T_TAG + j];
    float emH = emis[ebH + T_TAG + j];
    bool  kL  = MASK_AT(mbL + 1);
    bool  kH  = MASK_AT(mbH + 1);

    // ---- forward recursion ----
    for (int t = 1; t < S_LEN; t++) {
        // mN = max(alpha_{t-1}) from red (written before last barrier)
        float2 r0 = red_sh[rb], r1 = red_sh[rb + 1], r2 = red_sh[rb + 2], r3 = red_sh[rb + 3];
        const float mNL = fmaxf(fmaxf(r0.x, r1.x), fmaxf(r2.x, r3.x));
        const float mNH = fmaxf(fmaxf(r0.y, r1.y), fmaxf(r2.y, r3.y));

        // prefetch t+1
        float emNL = 0.f, emNH = 0.f;
        bool  kNL = false, kNH = false;
        if (t + 1 < S_LEN) {
            const size_t toff = (size_t)(t + 1) * T_TAG + j;
            emNL = emis[ebL + toff];
            emNH = emis[ebH + toff];
            kNL = MASK_AT(mbL + t + 1);
            kNH = MASK_AT(mbH + t + 1);
        }

        // ---- partial dot-products over my 64 i (all 4 batches, f32x2 packed) ----
        unsigned long long a01 = 0ull, a23 = 0ull, b01 = 0ull, b23 = 0ull;
        const ulonglong2* pp = (const ulonglong2*)p_sh;
#pragma unroll
        for (int ii = 0; ii < 64; ii += 2) {
            ulonglong2 pa = pp[ibase + ii];
            fma2(a01, E2[ii], pa.x);
            fma2(a23, E2[ii], pa.y);
            ulonglong2 pb = pp[ibase + ii + 1];
            fma2(b01, E2[ii + 1], pb.x);
            fma2(b23, E2[ii + 1], pb.y);
        }
        unsigned long long acc01 = add2(a01, b01);
        unsigned long long acc23 = add2(a23, b23);

        // exchange: store the pair I don't own, read my pair's other half
        if (g == 0) xch23[j] = acc23; else xch01[j] = acc01;
        __syncthreads();   // BAR1
        unsigned long long mine = (g == 0) ? acc01 : acc23;
        unsigned long long oth  = (g == 0) ? xch01[j] : xch23[j];
        float XL, XH;
        unpack2(add2(mine, oth), XL, XH);

        // alpha update for my two batches
        if (kL) aL = mnL + __logf(XL) + emL;
        if (kH) aH = mnH + __logf(XH) + emH;
        mnL = mNL; mnH = mNH;

        // p_next (my half of the float4) + per-warp maxes
        float2* pj = (float2*)&p_sh[j] + g;
        *pj = make_float2(__expf(aL - mnL), __expf(aH - mnH));
        float wl = warp_max(aL), wh = warp_max(aH);
        if (lane == 0) red_sh[wid] = make_float2(wl, wh);

        emL = emNL; emH = emNH; kL = kNL; kH = kNH;
        __syncthreads();   // BAR2: p + red visible
    }

    // ---- log_Z for my two batches ----
    float sL = warp_sum(__expf(aL - mnL));
    float sH = warp_sum(__expf(aH - mnH));
    if (lane == 0) red_sh[wid] = make_float2(sL, sH);
    __syncthreads();
    float zL, zH;
    {
        float2 r0 = red_sh[rb], r1 = red_sh[rb + 1], r2 = red_sh[rb + 2], r3 = red_sh[rb + 3];
        zL = mnL + __logf(r0.x + r1.x + r2.x + r3.x);
        zH = mnH + __logf(r0.y + r1.y + r2.y + r3.y);
    }

    // ---- gold score for my two batches ----
    float gL = 0.f, gH = 0.f;
    for (int tt = j; tt < S_LEN; tt += 128) {
        {
            int tg = TAG_AT(mbL + tt);
            bool mk = MASK_AT(mbL + tt);
            if (mk) gL += emis[ebL + (size_t)tt * T_TAG + tg];
            if (tt + 1 < S_LEN) {
                bool mk2 = MASK_AT(mbL + tt + 1);
                if (mk && mk2) gL += trans[tg * T_TAG + TAG_AT(mbL + tt + 1)];
            }
        }
        {
            int tg = TAG_AT(mbH + tt);
            bool mk = MASK_AT(mbH + tt);
            if (mk) gH += emis[ebH + (size_t)tt * T_TAG + tg];
            if (tt + 1 < S_LEN) {
                bool mk2 = MASK_AT(mbH + tt + 1);
                if (mk && mk2) gH += trans[tg * T_TAG + TAG_AT(mbH + tt + 1)];
            }
        }
    }
    __syncthreads();   // red_sh reads above complete
    gL = warp_sum(gL);
    gH = warp_sum(gH);
    if (lane == 0) red_sh[wid] = make_float2(gL, gH);
    __syncthreads();
    if (j == 0) {      // one thread per group (tid 0 and 128)
        float2 r0 = red_sh[rb], r1 = red_sh[rb + 1], r2 = red_sh[rb + 2], r3 = red_sh[rb + 3];
        float goldL = r0.x + r1.x + r2.x + r3.x;
        float goldH = r0.y + r1.y + r2.y + r3.y;
        scr[g] = (zL - goldL) + (zH - goldH);
    }
    __syncthreads();

    // ---- per-CTA partial + deterministic last-CTA final reduction ----
    if (tid == 0) {
        g_partial[blockIdx.x] = scr[0] + scr[1];
        __threadfence();
        int old = atomicAdd(&g_count, 1);
        is_last = (old == NCTA - 1) ? 1 : 0;
    }
    __syncthreads();
    if (is_last) {
        __threadfence();
        float v = (tid < NCTA) ? __ldcg(&g_partial[tid]) : 0.f;
        v = warp_sum(v);
        float* fin = (float*)red_sh;
        __syncthreads();
        if (lane == 0) fin[wid] = v;
        __syncthreads();
        if (tid == 0) {
            float tot = 0.f;
#pragma unroll
            for (int w = 0; w < 8; w++) tot += fin[w];
            out[0] = tot * (1.0f / (float)B_TOT);
            g_count = 0;   // reset for next graph replay
        }
    }
#undef MASK_AT
#undef TAG_AT
}

extern "C" void kernel_launch(void* const* d_in, const int* in_sizes, int n_in,
                              void* d_out, int out_size) {
    const float* emis  = (const float*)d_in[0];
    const void*  tags  = d_in[1];
    const void*  mask  = d_in[2];
    const float* trans = (const float*)d_in[3];
    float* out = (float*)d_out;

    crf_main<<<NCTA, NTHREADS>>>(emis, tags, mask, trans, out);
}

// round 6
// speedup vs baseline: 2.1779x; 1.4019x over previous
#include <cuda_runtime.h>
#include <cstdint>
#include <cstddef>

#define B_TOT 512
#define S_LEN 256
#define T_TAG 128
#define NB 4
#define NCTA 128
#define NTHREADS 256

__device__ float g_partial[NCTA];
__device__ int g_count = 0;

__device__ __forceinline__ float warp_max(float v) {
#pragma unroll
    for (int o = 16; o > 0; o >>= 1)
        v = fmaxf(v, __shfl_xor_sync(0xffffffffu, v, o));
    return v;
}
__device__ __forceinline__ float warp_sum(float v) {
#pragma unroll
    for (int o = 16; o > 0; o >>= 1)
        v += __shfl_xor_sync(0xffffffffu, v, o);
    return v;
}
__device__ __forceinline__ unsigned long long dup2(float e) {
    unsigned long long r;
    asm("mov.b64 %0, {%1, %1};" : "=l"(r) : "f"(e));
    return r;
}
__device__ __forceinline__ void fma2(unsigned long long& acc, unsigned long long a,
                                     unsigned long long b) {
    asm("fma.rn.f32x2 %0, %1, %2, %0;" : "+l"(acc) : "l"(a), "l"(b));
}
__device__ __forceinline__ unsigned long long add2(unsigned long long a,
                                                   unsigned long long b) {
    unsigned long long r;
    asm("add.rn.f32x2 %0, %1, %2;" : "=l"(r) : "l"(a), "l"(b));
    return r;
}
__device__ __forceinline__ void unpack2(unsigned long long v, float& lo, float& hi) {
    asm("mov.b64 {%0, %1}, %2;" : "=f"(lo), "=f"(hi) : "l"(v));
}

__global__ __launch_bounds__(NTHREADS, 1) void crf_main(
    const float* __restrict__ emis,
    const void* __restrict__ tags_raw,
    const void* __restrict__ mask_raw,
    const float* __restrict__ trans,
    float* __restrict__ out)
{
    __shared__ __align__(16) float4 p_sh[T_TAG];               // p, 4 batches per tag
    __shared__ __align__(16) unsigned long long xch[2][4][T_TAG]; // [pair][i-chunk][col]
    __shared__ float2 red_sh[8];
    __shared__ float scr[4];
    __shared__ float gred[8];
    __shared__ unsigned char msk[NB][S_LEN];
    __shared__ int is_last;

    const int tid  = threadIdx.x;
    const int lane = tid & 31;
    const int wid  = tid >> 5;
    // compute role: i-chunk g, column pair (col0, col0+1)
    const int g    = wid & 3;
    const int ch   = wid >> 2;
    const int col0 = ch * 64 + 2 * lane;
    // reduce role: batch pair p, column c
    const int p    = tid >> 7;
    const int c    = tid & 127;
    const int b0   = blockIdx.x * NB;

    // ---- dtype probes (input-derived, deterministic) ----
    const int* t32 = (const int*)tags_raw;
    const int tags_is_i32 = __syncthreads_or(t32[2 * tid + 1] != 0);
    const int* m32 = (const int*)mask_raw;
    const unsigned char* m8 = (const unsigned char*)mask_raw;
    const bool mask_is_u8 = (m32[0] == 0x01010101);

#define MASK_AT(idx) (mask_is_u8 ? (m8[idx] != 0) : (m32[idx] != 0))
#define TAG_AT(idx)  (tags_is_i32 ? t32[idx] : t32[2 * (idx)])

    // ---- E for my (i-chunk, 2 cols), pre-duplicated f32x2 ----
    unsigned long long E2[32][2];
#pragma unroll
    for (int ii = 0; ii < 32; ii++) {
        E2[ii][0] = dup2(__expf(trans[(g * 32 + ii) * T_TAG + col0]));
        E2[ii][1] = dup2(__expf(trans[(g * 32 + ii) * T_TAG + col0 + 1]));
    }

    // ---- mask preload to smem ----
    for (int idx = tid; idx < NB * S_LEN; idx += NTHREADS) {
        int nb = idx >> 8, tt = idx & 255;
        msk[nb][tt] = MASK_AT((size_t)(b0 + nb) * S_LEN + tt) ? 1 : 0;
    }

    const size_t ebL = (size_t)(b0 + 2 * p) * S_LEN * T_TAG;      // my low batch
    const size_t ebH = ebL + (size_t)S_LEN * T_TAG;               // my high batch

    // ---- alpha_0 ----
    float aL = emis[ebL + c];
    float aH = emis[ebH + c];
    float mnL, mnH;
    {
        float wl = warp_max(aL), wh = warp_max(aH);
        if (lane == 0) red_sh[wid] = make_float2(wl, wh);
        __syncthreads();   // also covers msk preload
        float2 r0 = red_sh[p * 4], r1 = red_sh[p * 4 + 1];
        float2 r2 = red_sh[p * 4 + 2], r3 = red_sh[p * 4 + 3];
        mnL = fmaxf(fmaxf(r0.x, r1.x), fmaxf(r2.x, r3.x));
        mnH = fmaxf(fmaxf(r0.y, r1.y), fmaxf(r2.y, r3.y));
        ((float2*)&p_sh[c])[p] = make_float2(__expf(aL - mnL), __expf(aH - mnH));
        __syncthreads();   // p + red (red reused as mN at t=1)
    }

    // prefetch t=1
    float emL = emis[ebL + T_TAG + c];
    float emH = emis[ebH + T_TAG + c];
    bool  kL  = msk[2 * p][1] != 0;
    bool  kH  = msk[2 * p + 1][1] != 0;

    // ---- forward recursion ----
    for (int t = 1; t < S_LEN; t++) {
        // mN = max(alpha_{t-1}) from red_sh (written before last barrier)
        float2 r0 = red_sh[p * 4], r1 = red_sh[p * 4 + 1];
        float2 r2 = red_sh[p * 4 + 2], r3 = red_sh[p * 4 + 3];
        const float mNL = fmaxf(fmaxf(r0.x, r1.x), fmaxf(r2.x, r3.x));
        const float mNH = fmaxf(fmaxf(r0.y, r1.y), fmaxf(r2.y, r3.y));

        // prefetch t+1
        float emNL = 0.f, emNH = 0.f;
        bool  kNL = false, kNH = false;
        if (t + 1 < S_LEN) {
            const size_t toff = (size_t)(t + 1) * T_TAG + c;
            emNL = emis[ebL + toff];
            emNH = emis[ebH + toff];
            kNL = msk[2 * p][t + 1] != 0;
            kNH = msk[2 * p + 1][t + 1] != 0;
        }

        // ---- partial dots: my i-chunk, 2 cols, both batch pairs ----
        unsigned long long a00 = 0ull, a01 = 0ull, a10 = 0ull, a11 = 0ull;
        const ulonglong2* pp = (const ulonglong2*)p_sh + g * 32;
#pragma unroll
        for (int ii = 0; ii < 32; ii++) {
            ulonglong2 pv = pp[ii];            // 16B broadcast: all 4 batches at tag i
            fma2(a00, E2[ii][0], pv.x);        // pair0, col0
            fma2(a10, E2[ii][0], pv.y);        // pair1, col0
            fma2(a01, E2[ii][1], pv.x);        // pair0, col1
            fma2(a11, E2[ii][1], pv.y);        // pair1, col1
        }
        {
            ulonglong2 v0; v0.x = a00; v0.y = a01;
            ulonglong2 v1; v1.x = a10; v1.y = a11;
            *(ulonglong2*)&xch[0][g][col0] = v0;   // conflict-free STS.128
            *(ulonglong2*)&xch[1][g][col0] = v1;
        }
        __syncthreads();   // BAR1: partials visible

        // ---- reduce 4 partials for my (pair, col) ----
        unsigned long long s0 = xch[p][0][c];
        unsigned long long s1 = xch[p][1][c];
        unsigned long long s2 = xch[p][2][c];
        unsigned long long s3 = xch[p][3][c];
        unsigned long long tot = add2(add2(s0, s1), add2(s2, s3));
        float XL, XH;
        unpack2(tot, XL, XH);

        if (kL) aL = mnL + __logf(XL) + emL;
        if (kH) aH = mnH + __logf(XH) + emH;
        mnL = mNL; mnH = mNH;

        ((float2*)&p_sh[c])[p] = make_float2(__expf(aL - mnL), __expf(aH - mnH));
        float wl = warp_max(aL), wh = warp_max(aH);
        if (lane == 0) red_sh[wid] = make_float2(wl, wh);

        emL = emNL; emH = emNH; kL = kNL; kH = kNH;
        __syncthreads();   // BAR2: p + red visible
    }

    // ---- log_Z ----
    float sL = warp_sum(__expf(aL - mnL));
    float sH = warp_sum(__expf(aH - mnH));
    if (lane == 0) red_sh[wid] = make_float2(sL, sH);
    __syncthreads();
    if (c == 0) {   // tid 0 and 128
        float2 r0 = red_sh[p * 4], r1 = red_sh[p * 4 + 1];
        float2 r2 = red_sh[p * 4 + 2], r3 = red_sh[p * 4 + 3];
        scr[2 * p]     = mnL + __logf(r0.x + r1.x + r2.x + r3.x);
        scr[2 * p + 1] = mnH + __logf(r0.y + r1.y + r2.y + r3.y);
    }

    // ---- gold: batch nb = tid>>6, 64 threads each ----
    {
        const int nb = tid >> 6;
        const int t0 = tid & 63;
        const size_t tb  = (size_t)(b0 + nb) * S_LEN;
        const size_t ebn = tb * T_TAG;
        float gg = 0.f;
        for (int tt = t0; tt < S_LEN; tt += 64) {
            int tg = TAG_AT(tb + tt);
            bool mk = msk[nb][tt] != 0;
            if (mk) gg += emis[ebn + (size_t)tt * T_TAG + tg];
            if (tt + 1 < S_LEN) {
                if (mk && msk[nb][tt + 1]) gg += trans[tg * T_TAG + TAG_AT(tb + tt + 1)];
            }
        }
        gg = warp_sum(gg);
        if (lane == 0) gred[wid] = gg;
    }
    __syncthreads();   // scr + gred visible

    if (tid == 0) {
        float part = 0.f;
#pragma unroll
        for (int nb = 0; nb < NB; nb++)
            part += scr[nb] - (gred[2 * nb] + gred[2 * nb + 1]);
        g_partial[blockIdx.x] = part;
        __threadfence();
        int old = atomicAdd(&g_count, 1);
        is_last = (old == NCTA - 1) ? 1 : 0;
    }
    __syncthreads();

    if (is_last) {
        __threadfence();
        float v = (tid < NCTA) ? __ldcg(&g_partial[tid]) : 0.f;
        v = warp_sum(v);
        if (lane == 0) gred[wid] = v;
        __syncthreads();
        if (tid == 0) {
            float tot = 0.f;
#pragma unroll
            for (int w = 0; w < 8; w++) tot += gred[w];
            out[0] = tot * (1.0f / (float)B_TOT);
            g_count = 0;   // reset for next graph replay
        }
    }
#undef MASK_AT
#undef TAG_AT
}

extern "C" void kernel_launch(void* const* d_in, const int* in_sizes, int n_in,
                              void* d_out, int out_size) {
    const float* emis  = (const float*)d_in[0];
    const void*  tags  = d_in[1];
    const void*  mask  = d_in[2];
    const float* trans = (const float*)d_in[3];
    float* out = (float*)d_out;

    crf_main<<<NCTA, NTHREADS>>>(emis, tags, mask, trans, out);
}